// round 14
// baseline (speedup 1.0000x reference)
#include <cuda_runtime.h>
#include <cuda_bf16.h>
#include <math_constants.h>

#define TOKENS (8 * 2048)
#define EDIM   512
#define NHEAD  64
#define DK     8

// fp16 operands for the output GEMM (1-term: fp16 quantization 2^-12 is enough)
__device__ unsigned short g_A[(size_t)TOKENS * EDIM];   // mid, fp16
__device__ unsigned short g_B[(size_t)EDIM * EDIM];     // W,  fp16

// ---- helpers --------------------------------------------------------------
__device__ __forceinline__ float ex2(float x) {
    float y; asm("ex2.approx.f32 %0, %1;" : "=f"(y) : "f"(x)); return y;
}
__device__ __forceinline__ float rcpa(float x) {
    float y; asm("rcp.approx.f32 %0, %1;" : "=f"(y) : "f"(x)); return y;
}
__device__ __forceinline__ unsigned cvtf16x2(float hi_, float lo_) {
    unsigned d;
    asm("cvt.rn.f16x2.f32 %0, %1, %2;" : "=r"(d) : "f"(hi_), "f"(lo_));
    return d;
}
__device__ __forceinline__ unsigned smem_u32(const void* p) {
    unsigned a;
    asm("{ .reg .u64 t; cvta.to.shared.u64 t, %1; cvt.u32.u64 %0, t; }" : "=r"(a) : "l"(p));
    return a;
}
__device__ __forceinline__ void cp16(unsigned dst, const void* src) {
    asm volatile("cp.async.cg.shared.global [%0], [%1], 16;" :: "r"(dst), "l"(src));
}
__device__ __forceinline__ void ldsm_x4(unsigned& r0, unsigned& r1, unsigned& r2,
                                        unsigned& r3, unsigned addr) {
    asm volatile("ldmatrix.sync.aligned.m8n8.x4.shared.b16 {%0,%1,%2,%3}, [%4];"
                 : "=r"(r0), "=r"(r1), "=r"(r2), "=r"(r3) : "r"(addr));
}
__device__ __forceinline__ void ldsm_x2(unsigned& r0, unsigned& r1, unsigned addr) {
    asm volatile("ldmatrix.sync.aligned.m8n8.x2.shared.b16 {%0,%1}, [%2];"
                 : "=r"(r0), "=r"(r1) : "r"(addr));
}
__device__ __forceinline__ void mma_f16(float* c, const unsigned* a,
                                        unsigned b0, unsigned b1) {
    asm volatile("mma.sync.aligned.m16n8k16.row.col.f32.f16.f16.f32 "
                 "{%0,%1,%2,%3}, {%4,%5,%6,%7}, {%8,%9}, {%0,%1,%2,%3};"
                 : "+f"(c[0]), "+f"(c[1]), "+f"(c[2]), "+f"(c[3])
                 : "r"(a[0]), "r"(a[1]), "r"(a[2]), "r"(a[3]), "r"(b0), "r"(b1));
}

#define SWZ64(o) ((o) ^ (((o) >> 3) & 0x30))

// ---------------------------------------------------------------------------
// Kernel A: tensor-core quantum attention, ALL-fp16 1-term (unchanged R11).
// ---------------------------------------------------------------------------
#define TOK_SZ 2304
#define PH_OFF 0
#define TH_OFF 1024

__global__ __launch_bounds__(256, 2) void qattn_tc(const float* __restrict__ x,
                                                   const float* __restrict__ theta,
                                                   const float* __restrict__ W) {
    __shared__ char sm[8 * TOK_SZ];

    const int tid = threadIdx.x;
    const int wid = tid >> 5;
    const int lid = tid & 31;

    // Folded W conversion to fp16
    if (blockIdx.x < 256) {
        const int idx = blockIdx.x * 256 + tid;
        const float4 w = ((const float4*)W)[idx];
        uint2 hu;
        hu.x = cvtf16x2(w.y, w.x);
        hu.y = cvtf16x2(w.w, w.z);
        ((uint2*)g_B)[idx] = hu;
    }

    const int token = blockIdx.x * 8 + wid;
    const unsigned base = smem_u32(sm) + wid * TOK_SZ;
    char* smp = sm + wid * TOK_SZ;

    float th[8];
    {
        const float4 t0 = ((const float4*)theta)[0];
        const float4 t1 = ((const float4*)theta)[1];
        th[0] = t0.x; th[1] = t0.y; th[2] = t0.z; th[3] = t0.w;
        th[4] = t1.x; th[5] = t1.y; th[6] = t1.z; th[7] = t1.w;
    }

    const float s = 0.7142224053f;   // sqrt((1/sqrt8)*log2e)

    {
        const float* xb = x + (size_t)token * EDIM + lid * 16;
        const float4 v0 = ((const float4*)xb)[0];
        const float4 v1 = ((const float4*)xb)[1];
        const float4 v2 = ((const float4*)xb)[2];
        const float4 v3 = ((const float4*)xb)[3];
        float pa[8], pb[8];
        pa[0] = __cosf(v0.x + th[0]); pa[1] = __cosf(v0.y + th[1]);
        pa[2] = __cosf(v0.z + th[2]); pa[3] = __cosf(v0.w + th[3]);
        pa[4] = __cosf(v1.x + th[4]); pa[5] = __cosf(v1.y + th[5]);
        pa[6] = __cosf(v1.z + th[6]); pa[7] = __cosf(v1.w + th[7]);
        pb[0] = __cosf(v2.x + th[0]); pb[1] = __cosf(v2.y + th[1]);
        pb[2] = __cosf(v2.z + th[2]); pb[3] = __cosf(v2.w + th[3]);
        pb[4] = __cosf(v3.x + th[4]); pb[5] = __cosf(v3.y + th[5]);
        pb[6] = __cosf(v3.z + th[6]); pb[7] = __cosf(v3.w + th[7]);

        #pragma unroll
        for (int d = 0; d < 8; d++) {
            *(unsigned*)(smp + TH_OFF + d * 144 + lid * 4) = cvtf16x2(pb[d], pa[d]);
        }

        uint4 row;
        row.x = cvtf16x2(pa[1] * s, pa[0] * s);
        row.y = cvtf16x2(pa[3] * s, pa[2] * s);
        row.z = cvtf16x2(pa[5] * s, pa[4] * s);
        row.w = cvtf16x2(pa[7] * s, pa[6] * s);
        *(uint4*)(smp + PH_OFF + (2 * lid) * 16) = row;
        row.x = cvtf16x2(pb[1] * s, pb[0] * s);
        row.y = cvtf16x2(pb[3] * s, pb[2] * s);
        row.z = cvtf16x2(pb[5] * s, pb[4] * s);
        row.w = cvtf16x2(pb[7] * s, pb[6] * s);
        *(uint4*)(smp + PH_OFF + (2 * lid + 1) * 16) = row;
    }
    __syncwarp();

    unsigned bT[4][2];
    #pragma unroll
    for (int t = 0; t < 2; t++) {
        const unsigned addrh = base + TH_OFF + (lid & 7) * 144 + t * 64 + (lid >> 3) * 16;
        ldsm_x4(bT[2 * t][0], bT[2 * t][1], bT[2 * t + 1][0], bT[2 * t + 1][1], addrh);
    }

    const int bI  = token >> 11;
    const int sbI = token & 2047;
    const size_t rowTail = (size_t)(bI * 2048) + (size_t)(sbI >> 6);
    const int colOff = (sbI & 63) * DK + 2 * (lid & 3);

    #pragma unroll 1
    for (int ms = 0; ms < 4; ms++) {
        unsigned ah4[4] = {0u, 0u, 0u, 0u};
        ldsm_x2(ah4[0], ah4[1], base + PH_OFF + (16 * ms + (lid & 15)) * 16);

        unsigned bh[8];
        ldsm_x4(bh[0], bh[1], bh[2], bh[3], base + PH_OFF + lid * 16);
        ldsm_x4(bh[4], bh[5], bh[6], bh[7], base + PH_OFF + (lid + 32) * 16);

        float c[8][4];
        #pragma unroll
        for (int nt = 0; nt < 8; nt++) {
            c[nt][0] = c[nt][1] = c[nt][2] = c[nt][3] = 0.f;
            mma_f16(c[nt], ah4, bh[nt], 0u);
        }

        float sum0 = 0.f, sum1 = 0.f;
        #pragma unroll
        for (int nt = 0; nt < 8; nt++) {
            c[nt][0] = ex2(c[nt][0]); c[nt][1] = ex2(c[nt][1]);
            c[nt][2] = ex2(c[nt][2]); c[nt][3] = ex2(c[nt][3]);
            sum0 += c[nt][0] + c[nt][1];
            sum1 += c[nt][2] + c[nt][3];
        }
        sum0 += __shfl_xor_sync(0xffffffffu, sum0, 1);
        sum0 += __shfl_xor_sync(0xffffffffu, sum0, 2);
        sum1 += __shfl_xor_sync(0xffffffffu, sum1, 1);
        sum1 += __shfl_xor_sync(0xffffffffu, sum1, 2);
        const float inv0 = rcpa(sum0);
        const float inv1 = rcpa(sum1);

        unsigned Eh[4][4];
        #pragma unroll
        for (int kt = 0; kt < 4; kt++) {
            const int n0 = 2 * kt, n1 = 2 * kt + 1;
            Eh[kt][0] = cvtf16x2(c[n0][1], c[n0][0]);
            Eh[kt][1] = cvtf16x2(c[n0][3], c[n0][2]);
            Eh[kt][2] = cvtf16x2(c[n1][1], c[n1][0]);
            Eh[kt][3] = cvtf16x2(c[n1][3], c[n1][2]);
        }

        float o[4] = {0.f, 0.f, 0.f, 0.f};
        #pragma unroll
        for (int kt = 0; kt < 4; kt++) {
            mma_f16(o, Eh[kt], bT[kt][0], bT[kt][1]);
        }
        o[0] *= inv0; o[1] *= inv0; o[2] *= inv1; o[3] *= inv1;

        const int h0 = 16 * ms + (lid >> 2);
        const size_t off0 = (rowTail + (size_t)(h0 * 32)) * EDIM + colOff;
        const size_t off1 = (rowTail + (size_t)((h0 + 8) * 32)) * EDIM + colOff;
        *(unsigned*)(g_A + off0) = cvtf16x2(o[1], o[0]);
        *(unsigned*)(g_A + off1) = cvtf16x2(o[3], o[2]);
    }
}

// ---------------------------------------------------------------------------
// Kernel B: 1-term fp16 GEMM, 3-stage cp.async pipeline, K-chunks of 64
// (8 chunks: per-chunk barrier/wait overhead halved vs K=32).
// Stage layout: 4 x 8KB SW64 sub-tiles [A k0-31 | A k32-63 | B k0-31 | B k32-63].
// 4 warps / 128 threads, warp tile 64x64 (2x2 warp grid).
// ---------------------------------------------------------------------------
#define TILE_B   8192
#define STAGE_B  32768
#define NSTAGE   3
#define NCHUNK   8
#define GSMEM_BYTES (NSTAGE * STAGE_B)

__device__ __forceinline__ void load_chunk(unsigned sb, int stage, int c,
                                           int rowBase, int colBase, int tid) {
    const unsigned base = sb + stage * STAGE_B;
    #pragma unroll
    for (int i = 0; i < 16; i++) {
        const int v    = i * 128 + tid;   // 0..2047
        const int tile = v >> 9;          // 0,1: A sub-chunks; 2,3: B (const per i)
        const int rem  = v & 511;
        const int r    = rem >> 2;
        const int c16  = rem & 3;
        const unsigned short* src;
        if (tile < 2) src = g_A + (size_t)(rowBase + r) * EDIM;
        else          src = g_B + (size_t)(colBase + r) * EDIM;
        src += c * 64 + (tile & 1) * 32 + c16 * 8;
        cp16(base + tile * TILE_B + SWZ64(r * 64 + c16 * 16), src);
    }
    asm volatile("cp.async.commit_group;" ::: "memory");
}

__global__ __launch_bounds__(128, 2) void out_gemm_mma(const float* __restrict__ bias,
                                                       float* __restrict__ out) {
    extern __shared__ char smem[];
    const unsigned sb = smem_u32(smem);
    const int tid = threadIdx.x;
    const int wid = tid >> 5;
    const int lid = tid & 31;

    const int rowBase = blockIdx.y * 128;
    const int colBase = blockIdx.x * 128;

    const int wy = wid & 1;    // m: 64 rows
    const int wx = wid >> 1;   // n: 64 cols

    const int lr  = lid & 7;
    const int sub = lid >> 3;

    float acc[4][8][4];
    #pragma unroll
    for (int mt = 0; mt < 4; mt++)
        #pragma unroll
        for (int nt = 0; nt < 8; nt++)
            #pragma unroll
            for (int q = 0; q < 4; q++) acc[mt][nt][q] = 0.f;

    load_chunk(sb, 0, 0, rowBase, colBase, tid);
    load_chunk(sb, 1, 1, rowBase, colBase, tid);

    int stage = 0;
    for (int c = 0; c < NCHUNK; c++) {
        if (c < NCHUNK - 1) {
            asm volatile("cp.async.wait_group 1;" ::: "memory");
        } else {
            asm volatile("cp.async.wait_group 0;" ::: "memory");
        }
        __syncthreads();

        const unsigned stg = sb + (unsigned)stage * STAGE_B;

        #pragma unroll
        for (int kk = 0; kk < 4; kk++) {
            const unsigned aTile = stg + (unsigned)(kk >> 1) * TILE_B;
            const unsigned bTile = stg + (unsigned)(2 + (kk >> 1)) * TILE_B;
            const int kb = (kk & 1) * 32;

            // A frags for 64 rows (4 m16 tiles)
            unsigned ah[4][4];
            #pragma unroll
            for (int mt = 0; mt < 4; mt++) {
                const int rowA = wy * 64 + mt * 16 + lr + (sub & 1) * 8;
                const int colb = kb + (sub >> 1) * 16;
                ldsm_x4(ah[mt][0], ah[mt][1], ah[mt][2], ah[mt][3],
                        aTile + SWZ64(rowA * 64 + colb));
            }

            // B frags for 64 cols (4 n16 tiles)
            unsigned bh[4][4];
            #pragma unroll
            for (int nt16 = 0; nt16 < 4; nt16++) {
                const int rowB = wx * 64 + nt16 * 16 + lr + (sub >> 1) * 8;
                const int colb = kb + (sub & 1) * 16;
                ldsm_x4(bh[nt16][0], bh[nt16][1], bh[nt16][2], bh[nt16][3],
                        bTile + SWZ64(rowB * 64 + colb));
            }

            #pragma unroll
            for (int nt16 = 0; nt16 < 4; nt16++)
                #pragma unroll
                for (int mt = 0; mt < 4; mt++) {
                    mma_f16(acc[mt][nt16 * 2],     ah[mt], bh[nt16][0], bh[nt16][1]);
                    mma_f16(acc[mt][nt16 * 2 + 1], ah[mt], bh[nt16][2], bh[nt16][3]);
                }
        }

        if (c + 2 < NCHUNK) {
            int fs = stage + 2;
            if (fs >= NSTAGE) fs -= NSTAGE;
            load_chunk(sb, fs, c + 2, rowBase, colBase, tid);
        }
        if (++stage == NSTAGE) stage = 0;
    }

    // epilogue: bias + store
    const int qrow = lid >> 2;
    const int qcol = (lid & 3) * 2;
    #pragma unroll
    for (int mt = 0; mt < 4; mt++) {
        #pragma unroll
        for (int nt = 0; nt < 8; nt++) {
            const int row = rowBase + wy * 64 + mt * 16 + qrow;
            const int col = colBase + wx * 64 + nt * 8 + qcol;
            const float2 bv = *(const float2*)&bias[col];
            float* o0 = out + (size_t)row * EDIM + col;
            float* o1 = o0 + 8 * EDIM;
            *(float2*)o0 = make_float2(acc[mt][nt][0] + bv.x, acc[mt][nt][1] + bv.y);
            *(float2*)o1 = make_float2(acc[mt][nt][2] + bv.x, acc[mt][nt][3] + bv.y);
        }
    }
}

// ---------------------------------------------------------------------------
extern "C" void kernel_launch(void* const* d_in, const int* in_sizes, int n_in,
                              void* d_out, int out_size) {
    const float* x     = (const float*)d_in[0];
    const float* theta = (const float*)d_in[1];
    const float* W     = (const float*)d_in[2];
    const float* bias  = (const float*)d_in[3];
    float* out = (float*)d_out;

    cudaFuncSetAttribute(out_gemm_mma, cudaFuncAttributeMaxDynamicSharedMemorySize,
                         GSMEM_BYTES);

    qattn_tc<<<TOKENS / 8, 256>>>(x, theta, W);

    dim3 grid(EDIM / 128, TOKENS / 128);   // (4, 128)
    out_gemm_mma<<<grid, 128, GSMEM_BYTES>>>(bias, out);
}

// round 15
// speedup vs baseline: 1.2078x; 1.2078x over previous
#include <cuda_runtime.h>
#include <cuda_bf16.h>
#include <math_constants.h>

#define TOKENS (8 * 2048)
#define EDIM   512
#define NHEAD  64
#define DK     8

// fp16 operands for the output GEMM (1-term: fp16 quantization 2^-12 is enough)
__device__ unsigned short g_A[(size_t)TOKENS * EDIM];   // mid, fp16
__device__ unsigned short g_B[(size_t)EDIM * EDIM];     // W,  fp16

// ---- helpers --------------------------------------------------------------
__device__ __forceinline__ float rcpa(float x) {
    float y; asm("rcp.approx.f32 %0, %1;" : "=f"(y) : "f"(x)); return y;
}
__device__ __forceinline__ unsigned cvtf16x2(float hi_, float lo_) {
    unsigned d;
    asm("cvt.rn.f16x2.f32 %0, %1, %2;" : "=r"(d) : "f"(hi_), "f"(lo_));
    return d;
}
__device__ __forceinline__ unsigned h2ex2(unsigned x) {   // packed fp16 2^x
    unsigned y; asm("ex2.approx.f16x2 %0, %1;" : "=r"(y) : "r"(x)); return y;
}
__device__ __forceinline__ unsigned smem_u32(const void* p) {
    unsigned a;
    asm("{ .reg .u64 t; cvta.to.shared.u64 t, %1; cvt.u32.u64 %0, t; }" : "=r"(a) : "l"(p));
    return a;
}
__device__ __forceinline__ void cp16(unsigned dst, const void* src) {
    asm volatile("cp.async.cg.shared.global [%0], [%1], 16;" :: "r"(dst), "l"(src));
}
__device__ __forceinline__ void ldsm_x4(unsigned& r0, unsigned& r1, unsigned& r2,
                                        unsigned& r3, unsigned addr) {
    asm volatile("ldmatrix.sync.aligned.m8n8.x4.shared.b16 {%0,%1,%2,%3}, [%4];"
                 : "=r"(r0), "=r"(r1), "=r"(r2), "=r"(r3) : "r"(addr));
}
__device__ __forceinline__ void ldsm_x2(unsigned& r0, unsigned& r1, unsigned addr) {
    asm volatile("ldmatrix.sync.aligned.m8n8.x2.shared.b16 {%0,%1}, [%2];"
                 : "=r"(r0), "=r"(r1) : "r"(addr));
}
__device__ __forceinline__ void mma_f16(float* c, const unsigned* a,
                                        unsigned b0, unsigned b1) {
    asm volatile("mma.sync.aligned.m16n8k16.row.col.f32.f16.f16.f32 "
                 "{%0,%1,%2,%3}, {%4,%5,%6,%7}, {%8,%9}, {%0,%1,%2,%3};"
                 : "+f"(c[0]), "+f"(c[1]), "+f"(c[2]), "+f"(c[3])
                 : "r"(a[0]), "r"(a[1]), "r"(a[2]), "r"(a[3]), "r"(b0), "r"(b1));
}

#define SWZ64(o) ((o) ^ (((o) >> 3) & 0x30))

// ---------------------------------------------------------------------------
// Kernel A: tensor-core quantum attention, fp16 1-term, packed-f16 ex2,
// MMA-based row sums (ones-column B-frag).
// ---------------------------------------------------------------------------
#define TOK_SZ 2304
#define PH_OFF 0
#define TH_OFF 1024

__global__ __launch_bounds__(256, 2) void qattn_tc(const float* __restrict__ x,
                                                   const float* __restrict__ theta,
                                                   const float* __restrict__ W) {
    __shared__ char sm[8 * TOK_SZ];

    const int tid = threadIdx.x;
    const int wid = tid >> 5;
    const int lid = tid & 31;

    // Folded W conversion to fp16
    if (blockIdx.x < 256) {
        const int idx = blockIdx.x * 256 + tid;
        const float4 w = ((const float4*)W)[idx];
        uint2 hu;
        hu.x = cvtf16x2(w.y, w.x);
        hu.y = cvtf16x2(w.w, w.z);
        ((uint2*)g_B)[idx] = hu;
    }

    const int token = blockIdx.x * 8 + wid;
    const unsigned base = smem_u32(sm) + wid * TOK_SZ;
    char* smp = sm + wid * TOK_SZ;

    float th[8];
    {
        const float4 t0 = ((const float4*)theta)[0];
        const float4 t1 = ((const float4*)theta)[1];
        th[0] = t0.x; th[1] = t0.y; th[2] = t0.z; th[3] = t0.w;
        th[4] = t1.x; th[5] = t1.y; th[6] = t1.z; th[7] = t1.w;
    }

    const float s = 0.7142224053f;   // sqrt((1/sqrt8)*log2e)

    {
        const float* xb = x + (size_t)token * EDIM + lid * 16;
        const float4 v0 = ((const float4*)xb)[0];
        const float4 v1 = ((const float4*)xb)[1];
        const float4 v2 = ((const float4*)xb)[2];
        const float4 v3 = ((const float4*)xb)[3];
        float pa[8], pb[8];
        pa[0] = __cosf(v0.x + th[0]); pa[1] = __cosf(v0.y + th[1]);
        pa[2] = __cosf(v0.z + th[2]); pa[3] = __cosf(v0.w + th[3]);
        pa[4] = __cosf(v1.x + th[4]); pa[5] = __cosf(v1.y + th[5]);
        pa[6] = __cosf(v1.z + th[6]); pa[7] = __cosf(v1.w + th[7]);
        pb[0] = __cosf(v2.x + th[0]); pb[1] = __cosf(v2.y + th[1]);
        pb[2] = __cosf(v2.z + th[2]); pb[3] = __cosf(v2.w + th[3]);
        pb[4] = __cosf(v3.x + th[4]); pb[5] = __cosf(v3.y + th[5]);
        pb[6] = __cosf(v3.z + th[6]); pb[7] = __cosf(v3.w + th[7]);

        #pragma unroll
        for (int d = 0; d < 8; d++) {
            *(unsigned*)(smp + TH_OFF + d * 144 + lid * 4) = cvtf16x2(pb[d], pa[d]);
        }

        uint4 row;
        row.x = cvtf16x2(pa[1] * s, pa[0] * s);
        row.y = cvtf16x2(pa[3] * s, pa[2] * s);
        row.z = cvtf16x2(pa[5] * s, pa[4] * s);
        row.w = cvtf16x2(pa[7] * s, pa[6] * s);
        *(uint4*)(smp + PH_OFF + (2 * lid) * 16) = row;
        row.x = cvtf16x2(pb[1] * s, pb[0] * s);
        row.y = cvtf16x2(pb[3] * s, pb[2] * s);
        row.z = cvtf16x2(pb[5] * s, pb[4] * s);
        row.w = cvtf16x2(pb[7] * s, pb[6] * s);
        *(uint4*)(smp + PH_OFF + (2 * lid + 1) * 16) = row;
    }
    __syncwarp();

    unsigned bT[4][2];
    #pragma unroll
    for (int t = 0; t < 2; t++) {
        const unsigned addrh = base + TH_OFF + (lid & 7) * 144 + t * 64 + (lid >> 3) * 16;
        ldsm_x4(bT[2 * t][0], bT[2 * t][1], bT[2 * t + 1][0], bT[2 * t + 1][1], addrh);
    }

    // ones-column B-frag for Z-sum MMA: B[k, n=0] = 1 for all k.
    // m16n8k16 B-frag: lane l holds n = l>>2 -> lanes 0..3 carry n=0.
    const unsigned bones = (lid < 4) ? 0x3C003C00u : 0u;

    const int bI  = token >> 11;
    const int sbI = token & 2047;
    const size_t rowTail = (size_t)(bI * 2048) + (size_t)(sbI >> 6);
    const int colOff = (sbI & 63) * DK + 2 * (lid & 3);

    #pragma unroll 1
    for (int ms = 0; ms < 4; ms++) {
        unsigned ah4[4] = {0u, 0u, 0u, 0u};
        ldsm_x2(ah4[0], ah4[1], base + PH_OFF + (16 * ms + (lid & 15)) * 16);

        unsigned bh[8];
        ldsm_x4(bh[0], bh[1], bh[2], bh[3], base + PH_OFF + lid * 16);
        ldsm_x4(bh[4], bh[5], bh[6], bh[7], base + PH_OFF + (lid + 32) * 16);

        float c[8][4];
        #pragma unroll
        for (int nt = 0; nt < 8; nt++) {
            c[nt][0] = c[nt][1] = c[nt][2] = c[nt][3] = 0.f;
            mma_f16(c[nt], ah4, bh[nt], 0u);
        }

        // E = exp2(f16(score)), computed as packed-f16 ex2 straight into A-frags
        unsigned Eh[4][4];
        #pragma unroll
        for (int kt = 0; kt < 4; kt++) {
            const int n0 = 2 * kt, n1 = 2 * kt + 1;
            Eh[kt][0] = h2ex2(cvtf16x2(c[n0][1], c[n0][0]));
            Eh[kt][1] = h2ex2(cvtf16x2(c[n0][3], c[n0][2]));
            Eh[kt][2] = h2ex2(cvtf16x2(c[n1][1], c[n1][0]));
            Eh[kt][3] = h2ex2(cvtf16x2(c[n1][3], c[n1][2]));
        }

        // attn slice = E @ T  and  Z = E @ ones (row sums, same fp16 E)
        float o[4] = {0.f, 0.f, 0.f, 0.f};
        float z[4] = {0.f, 0.f, 0.f, 0.f};
        #pragma unroll
        for (int kt = 0; kt < 4; kt++) {
            mma_f16(o, Eh[kt], bT[kt][0], bT[kt][1]);
            mma_f16(z, Eh[kt], bones, bones);
        }
        const float z0 = __shfl_sync(0xffffffffu, z[0], lid & 28);
        const float z1 = __shfl_sync(0xffffffffu, z[2], lid & 28);
        const float inv0 = rcpa(z0);
        const float inv1 = rcpa(z1);
        o[0] *= inv0; o[1] *= inv0; o[2] *= inv1; o[3] *= inv1;

        const int h0 = 16 * ms + (lid >> 2);
        const size_t off0 = (rowTail + (size_t)(h0 * 32)) * EDIM + colOff;
        const size_t off1 = (rowTail + (size_t)((h0 + 8) * 32)) * EDIM + colOff;
        *(unsigned*)(g_A + off0) = cvtf16x2(o[1], o[0]);
        *(unsigned*)(g_A + off1) = cvtf16x2(o[3], o[2]);
    }
}

// ---------------------------------------------------------------------------
// Kernel B: 1-term fp16 GEMM (exact R13 revert): 3-stage cp.async pipeline,
// K-chunks of 32, 4 warps / 128 threads, warp tile 64x64 (2x2 warp grid).
// ---------------------------------------------------------------------------
#define TILE_B   8192
#define STAGE_B  16384
#define NSTAGE   3
#define NCHUNK   16
#define GSMEM_BYTES (NSTAGE * STAGE_B)
#define A_T 0
#define B_T 1

__device__ __forceinline__ void load_chunk(unsigned sb, int stage, int c,
                                           int rowBase, int colBase, int tid) {
    const unsigned base = sb + stage * STAGE_B;
    #pragma unroll
    for (int i = 0; i < 8; i++) {
        const int v    = i * 128 + tid;   // 0..1023
        const int tile = v >> 9;          // 512 v16 per tile (constant per i)
        const int rem  = v & 511;
        const int r    = rem >> 2;
        const int c16  = rem & 3;
        const unsigned short* src;
        if (tile == 0) src = g_A + (size_t)(rowBase + r) * EDIM;
        else           src = g_B + (size_t)(colBase + r) * EDIM;
        src += c * 32 + c16 * 8;
        cp16(base + tile * TILE_B + SWZ64(r * 64 + c16 * 16), src);
    }
    asm volatile("cp.async.commit_group;" ::: "memory");
}

__global__ __launch_bounds__(128, 2) void out_gemm_mma(const float* __restrict__ bias,
                                                       float* __restrict__ out) {
    extern __shared__ char smem[];
    const unsigned sb = smem_u32(smem);
    const int tid = threadIdx.x;
    const int wid = tid >> 5;
    const int lid = tid & 31;

    const int rowBase = blockIdx.y * 128;
    const int colBase = blockIdx.x * 128;

    const int wy = wid & 1;    // m: 64 rows
    const int wx = wid >> 1;   // n: 64 cols

    const int lr  = lid & 7;
    const int sub = lid >> 3;

    float acc[4][8][4];
    #pragma unroll
    for (int mt = 0; mt < 4; mt++)
        #pragma unroll
        for (int nt = 0; nt < 8; nt++)
            #pragma unroll
            for (int q = 0; q < 4; q++) acc[mt][nt][q] = 0.f;

    load_chunk(sb, 0, 0, rowBase, colBase, tid);
    load_chunk(sb, 1, 1, rowBase, colBase, tid);

    int stage = 0;
    for (int c = 0; c < NCHUNK; c++) {
        if (c < NCHUNK - 1) {
            asm volatile("cp.async.wait_group 1;" ::: "memory");
        } else {
            asm volatile("cp.async.wait_group 0;" ::: "memory");
        }
        __syncthreads();

        const unsigned stg = sb + (unsigned)stage * STAGE_B;

        #pragma unroll
        for (int kk = 0; kk < 2; kk++) {
            const int kb = kk * 32;

            // A frags for 64 rows (4 m16 tiles)
            unsigned ah[4][4];
            #pragma unroll
            for (int mt = 0; mt < 4; mt++) {
                const int rowA = wy * 64 + mt * 16 + lr + (sub & 1) * 8;
                const int colb = kb + (sub >> 1) * 16;
                const unsigned off = SWZ64(rowA * 64 + colb);
                ldsm_x4(ah[mt][0], ah[mt][1], ah[mt][2], ah[mt][3], stg + A_T * TILE_B + off);
            }

            // B frags for 64 cols (4 n16 tiles)
            unsigned bh[4][4];
            #pragma unroll
            for (int nt16 = 0; nt16 < 4; nt16++) {
                const int rowB = wx * 64 + nt16 * 16 + lr + (sub >> 1) * 8;
                const int colb = kb + (sub & 1) * 16;
                const unsigned off = SWZ64(rowB * 64 + colb);
                ldsm_x4(bh[nt16][0], bh[nt16][1], bh[nt16][2], bh[nt16][3], stg + B_T * TILE_B + off);
            }

            #pragma unroll
            for (int nt16 = 0; nt16 < 4; nt16++)
                #pragma unroll
                for (int mt = 0; mt < 4; mt++) {
                    mma_f16(acc[mt][nt16 * 2],     ah[mt], bh[nt16][0], bh[nt16][1]);
                    mma_f16(acc[mt][nt16 * 2 + 1], ah[mt], bh[nt16][2], bh[nt16][3]);
                }
        }

        if (c + 2 < NCHUNK) {
            int fs = stage + 2;
            if (fs >= NSTAGE) fs -= NSTAGE;
            load_chunk(sb, fs, c + 2, rowBase, colBase, tid);
        }
        if (++stage == NSTAGE) stage = 0;
    }

    // epilogue: bias + store
    const int qrow = lid >> 2;
    const int qcol = (lid & 3) * 2;
    #pragma unroll
    for (int mt = 0; mt < 4; mt++) {
        #pragma unroll
        for (int nt = 0; nt < 8; nt++) {
            const int row = rowBase + wy * 64 + mt * 16 + qrow;
            const int col = colBase + wx * 64 + nt * 8 + qcol;
            const float2 bv = *(const float2*)&bias[col];
            float* o0 = out + (size_t)row * EDIM + col;
            float* o1 = o0 + 8 * EDIM;
            *(float2*)o0 = make_float2(acc[mt][nt][0] + bv.x, acc[mt][nt][1] + bv.y);
            *(float2*)o1 = make_float2(acc[mt][nt][2] + bv.x, acc[mt][nt][3] + bv.y);
        }
    }
}

// ---------------------------------------------------------------------------
extern "C" void kernel_launch(void* const* d_in, const int* in_sizes, int n_in,
                              void* d_out, int out_size) {
    const float* x     = (const float*)d_in[0];
    const float* theta = (const float*)d_in[1];
    const float* W     = (const float*)d_in[2];
    const float* bias  = (const float*)d_in[3];
    float* out = (float*)d_out;

    cudaFuncSetAttribute(out_gemm_mma, cudaFuncAttributeMaxDynamicSharedMemorySize,
                         GSMEM_BYTES);

    qattn_tc<<<TOKENS / 8, 256>>>(x, theta, W);

    dim3 grid(EDIM / 128, TOKENS / 128);   // (4, 128)
    out_gemm_mma<<<grid, 128, GSMEM_BYTES>>>(bias, out);
}